// round 1
// baseline (speedup 1.0000x reference)
#include <cuda_runtime.h>

#define NN   100000      // nodes
#define NE   1600000     // edges
#define NGR  128         // graphs
#define D_   128         // hidden dim
#define DO_  64          // output dim
#define BN_EPS 1e-5f

// ---------------- scratch (device globals: allocation-free) ----------------
__device__ __align__(16) float g_agg[(size_t)NN * D_];
__device__ __align__(16) float g_hid[(size_t)NN * D_];
__device__ __align__(16) float g_h1 [(size_t)NN * D_];
__device__ __align__(16) float g_h2 [(size_t)NN * D_];
__device__ __align__(16) float g_bnstats[2 * D_];   // [sum(0..NOUT), sqsum(NOUT..2*NOUT)]
__device__ __align__(16) float g_scale[D_];
__device__ __align__(16) float g_shift[D_];
__device__ __align__(16) float g_pool[NGR * DO_];
__device__ __align__(16) int   g_cnt[NGR];

// ---------------- small utility kernels ----------------
__global__ void zero_kernel(float* __restrict__ p, int n4) {
    int i = blockIdx.x * blockDim.x + threadIdx.x;
    if (i < n4) ((float4*)p)[i] = make_float4(0.f, 0.f, 0.f, 0.f);
}

__global__ void copy_kernel(float* __restrict__ dst, const float* __restrict__ src, int n4) {
    int i = blockIdx.x * blockDim.x + threadIdx.x;
    if (i < n4) ((float4*)dst)[i] = ((const float4*)src)[i];
}

// ---------------- edge scatter: agg[dst] += h[src], one warp per edge ----------------
__global__ void scatter_kernel(const float* __restrict__ h,
                               const int* __restrict__ src,
                               const int* __restrict__ dst,
                               float* __restrict__ agg)
{
    int e = (blockIdx.x << 3) + (threadIdx.x >> 5);
    if (e >= NE) return;
    int lane = threadIdx.x & 31;
    int s = __ldg(src + e);
    int d = __ldg(dst + e);
    float4 v = *(const float4*)(h + (size_t)s * D_ + (lane << 2));
    float* p = agg + (size_t)d * D_ + (lane << 2);
    asm volatile("red.global.add.v4.f32 [%0], {%1, %2, %3, %4};"
                 :: "l"(p), "f"(v.x), "f"(v.y), "f"(v.z), "f"(v.w) : "memory");
}

// ---------------- fp32 GEMM: out[N,NOUT] = A[N,128] @ W[128,NOUT] + bias ----------------
// 128x NOUT block tile, 256 threads, 8x(NOUT/16) micro-tile, full K=128 in smem.
// Optional fused ReLU; optional fused BatchNorm statistics (col sum / sumsq).
template<int NOUT, bool RELU, bool STATS>
__global__ __launch_bounds__(256, 1)
void gemm_kernel(const float* __restrict__ A, const float* __restrict__ W,
                 const float* __restrict__ bias, float* __restrict__ out)
{
    extern __shared__ float smem[];
    float* As   = smem;                      // 128*128
    float* Ws   = smem + 128 * 128;          // 128*NOUT
    float* s_sum = Ws + 128 * NOUT;          // NOUT
    float* s_sq  = s_sum + NOUT;             // NOUT

    const int tid  = threadIdx.x;
    const int row0 = blockIdx.x * 128;

    // load W (full) into smem
    for (int i = tid; i < 128 * NOUT / 4; i += 256)
        ((float4*)Ws)[i] = ((const float4*)W)[i];

    // load A tile (row-guarded, zero-fill)
    for (int i = tid; i < 128 * 128 / 4; i += 256) {
        int r  = i >> 5;
        int gr = row0 + r;
        float4 v = make_float4(0.f, 0.f, 0.f, 0.f);
        if (gr < NN) v = *(const float4*)(A + (size_t)gr * 128 + ((i & 31) << 2));
        ((float4*)As)[i] = v;
    }
    if (STATS) {
        for (int i = tid; i < NOUT; i += 256) { s_sum[i] = 0.f; s_sq[i] = 0.f; }
    }
    __syncthreads();

    const int tr = tid >> 4;       // 0..15 (row group)
    const int tc = tid & 15;       // 0..15 (col group)
    const int r0 = tr * 8;
    constexpr int CPT = NOUT / 16; // cols/thread: 8 (NOUT=128) or 4 (NOUT=64)
    constexpr int NG  = CPT / 4;   // float4 col groups: 2 or 1

    float acc[8][CPT];
    #pragma unroll
    for (int i = 0; i < 8; i++)
        #pragma unroll
        for (int j = 0; j < CPT; j++) acc[i][j] = 0.f;

    for (int k0 = 0; k0 < 128; k0 += 4) {
        float4 a4[8];
        #pragma unroll
        for (int i = 0; i < 8; i++)
            a4[i] = *(const float4*)(As + (r0 + i) * 128 + k0);
        #pragma unroll
        for (int kk = 0; kk < 4; kk++) {
            float b[CPT];
            #pragma unroll
            for (int g = 0; g < NG; g++) {
                float4 bv4 = *(const float4*)(Ws + (k0 + kk) * NOUT + g * 64 + tc * 4);
                b[g*4+0] = bv4.x; b[g*4+1] = bv4.y; b[g*4+2] = bv4.z; b[g*4+3] = bv4.w;
            }
            #pragma unroll
            for (int i = 0; i < 8; i++) {
                float a = (kk == 0) ? a4[i].x : (kk == 1) ? a4[i].y
                        : (kk == 2) ? a4[i].z : a4[i].w;
                #pragma unroll
                for (int j = 0; j < CPT; j++)
                    acc[i][j] = fmaf(a, b[j], acc[i][j]);
            }
        }
    }

    // bias (per-thread columns)
    float bv[CPT];
    #pragma unroll
    for (int g = 0; g < NG; g++) {
        float4 t = *(const float4*)(bias + g * 64 + tc * 4);
        bv[g*4+0] = t.x; bv[g*4+1] = t.y; bv[g*4+2] = t.z; bv[g*4+3] = t.w;
    }

    float csum[CPT], csq[CPT];
    #pragma unroll
    for (int j = 0; j < CPT; j++) { csum[j] = 0.f; csq[j] = 0.f; }

    #pragma unroll
    for (int i = 0; i < 8; i++) {
        int gr = row0 + r0 + i;
        if (gr >= NN) continue;
        #pragma unroll
        for (int g = 0; g < NG; g++) {
            float4 o;
            float* op = (float*)&o;
            #pragma unroll
            for (int j = 0; j < 4; j++) {
                float v = acc[i][g*4+j] + bv[g*4+j];
                if (RELU) v = fmaxf(v, 0.f);
                op[j] = v;
                if (STATS) { csum[g*4+j] += v; csq[g*4+j] += v * v; }
            }
            *(float4*)(out + (size_t)gr * NOUT + g * 64 + tc * 4) = o;
        }
    }

    if (STATS) {
        #pragma unroll
        for (int g = 0; g < NG; g++)
            #pragma unroll
            for (int j = 0; j < 4; j++) {
                int c = g * 64 + tc * 4 + j;
                atomicAdd(&s_sum[c], csum[g*4+j]);
                atomicAdd(&s_sq[c],  csq[g*4+j]);
            }
        __syncthreads();
        if (tid < NOUT) {
            atomicAdd(&g_bnstats[tid], s_sum[tid]);
            atomicAdd(&g_bnstats[NOUT + tid], s_sq[tid]);
        }
    }
}

// ---------------- BN finalize: scale/shift from accumulated stats ----------------
__global__ void bn_finalize_kernel(const float* __restrict__ gamma,
                                   const float* __restrict__ beta, int nout)
{
    int c = threadIdx.x;
    if (c < nout) {
        const float invN = 1.0f / (float)NN;
        float mu  = g_bnstats[c] * invN;
        float var = g_bnstats[nout + c] * invN - mu * mu;
        float s   = gamma[c] * rsqrtf(var + BN_EPS);
        g_scale[c] = s;
        g_shift[c] = beta[c] - mu * s;
    }
}

// ---------------- apply BN + ReLU; optionally also seed next layer's agg ----------------
template<int NOUT, bool WRITE_AGG>
__global__ void bn_apply_kernel(const float* __restrict__ pre,
                                float* __restrict__ hout,
                                float* __restrict__ aggout)
{
    int i = blockIdx.x * blockDim.x + threadIdx.x;
    const int total4 = NN * NOUT / 4;
    if (i >= total4) return;
    int c = (i * 4) & (NOUT - 1);
    float4 v  = ((const float4*)pre)[i];
    float4 sc = *(const float4*)(g_scale + c);
    float4 sh = *(const float4*)(g_shift + c);
    float4 r;
    r.x = fmaxf(fmaf(v.x, sc.x, sh.x), 0.f);
    r.y = fmaxf(fmaf(v.y, sc.y, sh.y), 0.f);
    r.z = fmaxf(fmaf(v.z, sc.z, sh.z), 0.f);
    r.w = fmaxf(fmaf(v.w, sc.w, sh.w), 0.f);
    ((float4*)hout)[i] = r;
    if (WRITE_AGG) ((float4*)aggout)[i] = r;
}

// ---------------- pooling ----------------
__global__ void pool_sum_kernel(const float* __restrict__ h, const int* __restrict__ batch)
{
    int t = blockIdx.x * blockDim.x + threadIdx.x;
    if (t >= NN * (DO_ / 4)) return;
    int n = t >> 4;      // DO_/4 = 16 quads per node
    int q = t & 15;
    int b = __ldg(batch + n);
    float4 v = *(const float4*)(h + (size_t)n * DO_ + (q << 2));
    float* p = g_pool + b * DO_ + (q << 2);
    asm volatile("red.global.add.v4.f32 [%0], {%1, %2, %3, %4};"
                 :: "l"(p), "f"(v.x), "f"(v.y), "f"(v.z), "f"(v.w) : "memory");
}

__global__ void pool_cnt_kernel(const int* __restrict__ batch)
{
    __shared__ int sc[NGR];
    for (int i = threadIdx.x; i < NGR; i += blockDim.x) sc[i] = 0;
    __syncthreads();
    for (int i = blockIdx.x * blockDim.x + threadIdx.x; i < NN; i += gridDim.x * blockDim.x)
        atomicAdd(&sc[__ldg(batch + i)], 1);
    __syncthreads();
    for (int i = threadIdx.x; i < NGR; i += blockDim.x)
        if (sc[i]) atomicAdd(&g_cnt[i], sc[i]);
}

__global__ void pool_fin_kernel(float* __restrict__ out)
{
    int i = blockIdx.x * blockDim.x + threadIdx.x;
    if (i < NGR * DO_) {
        int g = i >> 6;
        float c = (float)(g_cnt[g] > 0 ? g_cnt[g] : 1);
        out[i] = g_pool[i] / c;
    }
}

// ---------------- launcher ----------------
extern "C" void kernel_launch(void* const* d_in, const int* in_sizes, int n_in,
                              void* d_out, int out_size)
{
    const float* x     = (const float*)d_in[0];
    const int*   ei    = (const int*)d_in[1];
    const int*   batch = (const int*)d_in[2];
    const float *wA[3], *bA[3], *wB[3], *bB[3], *gam[3], *bet[3];
    for (int l = 0; l < 3; l++) {
        wA[l]  = (const float*)d_in[3 + 6*l + 0];
        bA[l]  = (const float*)d_in[3 + 6*l + 1];
        wB[l]  = (const float*)d_in[3 + 6*l + 2];
        bB[l]  = (const float*)d_in[3 + 6*l + 3];
        gam[l] = (const float*)d_in[3 + 6*l + 4];
        bet[l] = (const float*)d_in[3 + 6*l + 5];
    }
    const int* src = ei;
    const int* dst = ei + NE;

    float *agg, *hid, *h1, *h2, *bnst, *pool;
    int* cnt;
    cudaGetSymbolAddress((void**)&agg,  g_agg);
    cudaGetSymbolAddress((void**)&hid,  g_hid);
    cudaGetSymbolAddress((void**)&h1,   g_h1);
    cudaGetSymbolAddress((void**)&h2,   g_h2);
    cudaGetSymbolAddress((void**)&bnst, g_bnstats);
    cudaGetSymbolAddress((void**)&pool, g_pool);
    cudaGetSymbolAddress((void**)&cnt,  g_cnt);

    constexpr int SM128 = (128*128 + 128*128 + 2*128) * 4;  // 132096 B
    constexpr int SM64  = (128*128 + 128*64  + 2*64 ) * 4;  //  98816 B
    cudaFuncSetAttribute(gemm_kernel<128, true,  false>, cudaFuncAttributeMaxDynamicSharedMemorySize, SM128);
    cudaFuncSetAttribute(gemm_kernel<128, false, true >, cudaFuncAttributeMaxDynamicSharedMemorySize, SM128);
    cudaFuncSetAttribute(gemm_kernel<64,  false, true >, cudaFuncAttributeMaxDynamicSharedMemorySize, SM64);

    const int GB   = (NN + 127) / 128;            // 782 row blocks
    const int EW4  = (NN * D_ / 4 + 255) / 256;   // elementwise grid (d=128)
    const int EW64 = (NN * DO_ / 4 + 255) / 256;  // elementwise grid (d=64)
    const int SCG  = (NE + 7) / 8;                // scatter grid (8 edges/block)

    // zero pool accumulators
    zero_kernel<<<(NGR * DO_ / 4 + 255) / 256, 256>>>(pool, NGR * DO_ / 4);
    zero_kernel<<<1, 32>>>((float*)cnt, NGR / 4);

    // ---- layer 0 (input x) ----
    copy_kernel<<<EW4, 256>>>(agg, x, NN * D_ / 4);
    scatter_kernel<<<SCG, 256>>>(x, src, dst, agg);
    gemm_kernel<128, true,  false><<<GB, 256, SM128>>>(agg, wA[0], bA[0], hid);
    zero_kernel<<<1, 64>>>(bnst, 64);
    gemm_kernel<128, false, true ><<<GB, 256, SM128>>>(hid, wB[0], bB[0], agg);
    bn_finalize_kernel<<<1, 128>>>(gam[0], bet[0], 128);
    bn_apply_kernel<128, true><<<EW4, 256>>>(agg, h1, agg);   // agg := h1 (next agg-init)

    // ---- layer 1 ----
    scatter_kernel<<<SCG, 256>>>(h1, src, dst, agg);
    gemm_kernel<128, true,  false><<<GB, 256, SM128>>>(agg, wA[1], bA[1], hid);
    zero_kernel<<<1, 64>>>(bnst, 64);
    gemm_kernel<128, false, true ><<<GB, 256, SM128>>>(hid, wB[1], bB[1], agg);
    bn_finalize_kernel<<<1, 128>>>(gam[1], bet[1], 128);
    bn_apply_kernel<128, true><<<EW4, 256>>>(agg, h2, agg);   // agg := h2

    // ---- layer 2 (output dim 64) ----
    scatter_kernel<<<SCG, 256>>>(h2, src, dst, agg);
    gemm_kernel<128, true,  false><<<GB, 256, SM128>>>(agg, wA[2], bA[2], hid);
    zero_kernel<<<1, 64>>>(bnst, 64);
    gemm_kernel<64,  false, true ><<<GB, 256, SM64 >>>(hid, wB[2], bB[2], agg);
    bn_finalize_kernel<<<1, 64>>>(gam[2], bet[2], 64);
    bn_apply_kernel<64, false><<<EW64, 256>>>(agg, h1, (float*)0);

    // ---- global mean pool ----
    pool_sum_kernel<<<(NN * (DO_ / 4) + 255) / 256, 256>>>(h1, batch);
    pool_cnt_kernel<<<296, 256>>>(batch);
    pool_fin_kernel<<<(NGR * DO_ + 255) / 256, 256>>>((float*)d_out);
}

// round 2
// speedup vs baseline: 1.1966x; 1.1966x over previous
#include <cuda_runtime.h>

#define NN   100000      // nodes
#define NE   1600000     // edges
#define NGR  128         // graphs
#define D_   128         // hidden dim
#define DO_  64          // output dim
#define BN_EPS 1e-5f
#define SCAN_ELEMS 2048
#define NBLK ((NN + SCAN_ELEMS - 1) / SCAN_ELEMS)   // 49

typedef unsigned long long ull;

// ---------------- scratch (device globals: allocation-free) ----------------
__device__ __align__(16) float g_agg[(size_t)NN * D_];
__device__ __align__(16) float g_hid[(size_t)NN * D_];
__device__ __align__(16) float g_h1 [(size_t)NN * D_];
__device__ __align__(16) float g_h2 [(size_t)NN * D_];
__device__ __align__(16) float g_bnstats[2 * D_];
__device__ __align__(16) float g_scale[D_];
__device__ __align__(16) float g_shift[D_];
__device__ __align__(16) float g_pool[NGR * DO_];
__device__ __align__(16) int   g_cnt[NGR];
// CSR scratch
__device__ __align__(16) int g_deg[NN];
__device__ __align__(16) int g_off[NN + 1];
__device__ __align__(16) int g_cur[NN];
__device__ __align__(16) int g_csr[NE];
__device__ int g_bsum[64];
__device__ int g_bscan[64];

// ---------------- f32x2 helpers ----------------
__device__ __forceinline__ ull fma2(ull a, ull b, ull c) {
    ull r;
    asm("fma.rn.f32x2 %0, %1, %2, %3;" : "=l"(r) : "l"(a), "l"(b), "l"(c));
    return r;
}
__device__ __forceinline__ void unpack2(ull p, float& lo, float& hi) {
    asm("mov.b64 {%0, %1}, %2;" : "=f"(lo), "=f"(hi) : "l"(p));
}

// ---------------- small utility kernels ----------------
__global__ void zero_kernel(float* __restrict__ p, int n4) {
    int i = blockIdx.x * blockDim.x + threadIdx.x;
    if (i < n4) ((float4*)p)[i] = make_float4(0.f, 0.f, 0.f, 0.f);
}

// ---------------- CSR build ----------------
__global__ void hist_kernel(const int* __restrict__ dst) {
    int i = blockIdx.x * blockDim.x + threadIdx.x;
    if (i < NE) atomicAdd(&g_deg[__ldg(dst + i)], 1);
}

__global__ void scan_pass1() {   // per-chunk totals
    __shared__ int ssum[8];
    int b = blockIdx.x, tid = threadIdx.x;
    int base = b * SCAN_ELEMS + tid * 8;
    int s = 0;
    #pragma unroll
    for (int j = 0; j < 8; j++) {
        int idx = base + j;
        s += (idx < NN) ? g_deg[idx] : 0;
    }
    #pragma unroll
    for (int o = 16; o; o >>= 1) s += __shfl_down_sync(0xffffffffu, s, o);
    if ((tid & 31) == 0) ssum[tid >> 5] = s;
    __syncthreads();
    if (tid == 0) {
        int t = 0;
        #pragma unroll
        for (int i = 0; i < 8; i++) t += ssum[i];
        g_bsum[b] = t;
    }
}

__global__ void scan_pass2() {   // exclusive scan of chunk totals (1 block, 64 thr)
    int tid = threadIdx.x;
    int v = (tid < NBLK) ? g_bsum[tid] : 0;
    int incl = v;
    int lane = tid & 31;
    #pragma unroll
    for (int o = 1; o < 32; o <<= 1) {
        int y = __shfl_up_sync(0xffffffffu, incl, o);
        if (lane >= o) incl += y;
    }
    __shared__ int w0;
    if (tid == 31) w0 = incl;
    __syncthreads();
    if (tid >= 32) incl += w0;
    if (tid < 64) g_bscan[tid] = incl - v;
    if (tid == 0) g_off[NN] = NE;
}

__global__ void scan_pass3() {   // write exclusive offsets + cursors
    int b = blockIdx.x, tid = threadIdx.x;
    int base = b * SCAN_ELEMS + tid * 8;
    int vals[8];
    int t = 0;
    #pragma unroll
    for (int j = 0; j < 8; j++) {
        vals[j] = (base + j < NN) ? g_deg[base + j] : 0;
        t += vals[j];
    }
    // block exclusive scan of thread totals
    int lane = tid & 31, wid = tid >> 5;
    int incl = t;
    #pragma unroll
    for (int o = 1; o < 32; o <<= 1) {
        int y = __shfl_up_sync(0xffffffffu, incl, o);
        if (lane >= o) incl += y;
    }
    __shared__ int wsum[8], woff[8];
    if (lane == 31) wsum[wid] = incl;
    __syncthreads();
    if (tid == 0) {
        int a = 0;
        #pragma unroll
        for (int i = 0; i < 8; i++) { woff[i] = a; a += wsum[i]; }
    }
    __syncthreads();
    int run = g_bscan[b] + woff[wid] + (incl - t);
    #pragma unroll
    for (int j = 0; j < 8; j++) {
        int idx = base + j;
        if (idx < NN) { g_off[idx] = run; g_cur[idx] = run; run += vals[j]; }
    }
}

__global__ void fill_kernel(const int* __restrict__ src, const int* __restrict__ dst) {
    int i = blockIdx.x * blockDim.x + threadIdx.x;
    if (i < NE) {
        int d = __ldg(dst + i);
        int p = atomicAdd(&g_cur[d], 1);
        g_csr[p] = __ldg(src + i);
    }
}

// ---------------- gather: agg[i] = f(h[i]) + sum_{j in N(i)} f(h[j]) ----------------
// f = identity (layer 0) or BN+ReLU of the previous layer (fused, g_scale/g_shift)
template<bool BN>
__device__ __forceinline__ float4 bn_f(float4 v, float4 sc, float4 sh) {
    if (BN) {
        v.x = fmaxf(fmaf(v.x, sc.x, sh.x), 0.f);
        v.y = fmaxf(fmaf(v.y, sc.y, sh.y), 0.f);
        v.z = fmaxf(fmaf(v.z, sc.z, sh.z), 0.f);
        v.w = fmaxf(fmaf(v.w, sc.w, sh.w), 0.f);
    }
    return v;
}
__device__ __forceinline__ void f4acc(float4& a, float4 b) {
    a.x += b.x; a.y += b.y; a.z += b.z; a.w += b.w;
}

template<bool BN>
__global__ void gather_kernel(const float* __restrict__ h, float* __restrict__ out)
{
    int n = blockIdx.x * 8 + (threadIdx.x >> 5);
    if (n >= NN) return;
    int lane = threadIdx.x & 31;
    const float4* __restrict__ h4 = (const float4*)h;

    float4 sc = make_float4(0,0,0,0), sh = make_float4(0,0,0,0);
    if (BN) {
        sc = *(const float4*)(g_scale + lane * 4);
        sh = *(const float4*)(g_shift + lane * 4);
    }

    float4 a0 = bn_f<BN>(__ldg(&h4[(size_t)n * 32 + lane]), sc, sh);  // self term
    float4 a1 = make_float4(0,0,0,0);

    int e0 = g_off[n], e1 = g_off[n + 1];
    for (int base = e0; base < e1; base += 32) {
        int e = base + lane;
        int idx = (e < e1) ? __ldg(&g_csr[e]) : 0;
        int cnt = min(32, e1 - base);
        int j = 0;
        for (; j + 4 <= cnt; j += 4) {
            int s0 = __shfl_sync(0xffffffffu, idx, j);
            int s1 = __shfl_sync(0xffffffffu, idx, j + 1);
            int s2 = __shfl_sync(0xffffffffu, idx, j + 2);
            int s3 = __shfl_sync(0xffffffffu, idx, j + 3);
            float4 w0 = __ldg(&h4[(size_t)s0 * 32 + lane]);
            float4 w1 = __ldg(&h4[(size_t)s1 * 32 + lane]);
            float4 w2 = __ldg(&h4[(size_t)s2 * 32 + lane]);
            float4 w3 = __ldg(&h4[(size_t)s3 * 32 + lane]);
            f4acc(a0, bn_f<BN>(w0, sc, sh));
            f4acc(a1, bn_f<BN>(w1, sc, sh));
            f4acc(a0, bn_f<BN>(w2, sc, sh));
            f4acc(a1, bn_f<BN>(w3, sc, sh));
        }
        for (; j < cnt; j++) {
            int s = __shfl_sync(0xffffffffu, idx, j);
            f4acc(a0, bn_f<BN>(__ldg(&h4[(size_t)s * 32 + lane]), sc, sh));
        }
    }
    f4acc(a0, a1);
    ((float4*)out)[(size_t)n * 32 + lane] = a0;
}

// ---------------- fp32x2 GEMM: out[N,NOUT] = A[N,128] @ W[128,NOUT] + bias ----------------
// 128 x NOUT block tile, 256 threads, K packed in f32x2 pairs (FFMA2).
// W transposed in smem with stride 130 (conflict-free LDS.64).
template<int NOUT, bool RELU, bool STATS>
__global__ __launch_bounds__(256, 1)
void gemm_kernel(const float* __restrict__ A, const float* __restrict__ W,
                 const float* __restrict__ bias, float* __restrict__ out)
{
    constexpr int WS = 130;
    constexpr int CPT = NOUT / 16;   // 8 or 4 cols per thread
    extern __shared__ float smem[];
    float* As    = smem;                   // 128*128
    float* Ws    = smem + 128 * 128;       // NOUT*WS (transposed: Ws[col*WS + k])
    float* s_sum = Ws + NOUT * WS;
    float* s_sq  = s_sum + NOUT;

    const int tid  = threadIdx.x;
    const int row0 = blockIdx.x * 128;

    // W -> smem transposed
    for (int i = tid; i < 128 * NOUT / 4; i += 256) {
        int k = (i * 4) / NOUT;
        int c = (i * 4) % NOUT;
        float4 w4 = ((const float4*)W)[i];
        Ws[(c + 0) * WS + k] = w4.x;
        Ws[(c + 1) * WS + k] = w4.y;
        Ws[(c + 2) * WS + k] = w4.z;
        Ws[(c + 3) * WS + k] = w4.w;
    }
    // A tile (row-guarded)
    for (int i = tid; i < 128 * 128 / 4; i += 256) {
        int r = i >> 5, gr = row0 + r;
        float4 v = make_float4(0.f, 0.f, 0.f, 0.f);
        if (gr < NN) v = ((const float4*)A)[(size_t)gr * 32 + (i & 31)];
        ((float4*)As)[i] = v;
    }
    if (STATS) for (int i = tid; i < NOUT; i += 256) { s_sum[i] = 0.f; s_sq[i] = 0.f; }
    __syncthreads();

    const int tr = tid >> 4;
    const int tc = tid & 15;
    const int r0 = tr * 8;

    ull acc[8][CPT];
    #pragma unroll
    for (int i = 0; i < 8; i++)
        #pragma unroll
        for (int j = 0; j < CPT; j++) acc[i][j] = 0ull;

    #pragma unroll 2
    for (int kp = 0; kp < 64; kp++) {
        ull a2[8], b2[CPT];
        #pragma unroll
        for (int i = 0; i < 8; i++)
            a2[i] = *(const ull*)(As + (r0 + i) * 128 + 2 * kp);
        #pragma unroll
        for (int j = 0; j < CPT; j++)
            b2[j] = *(const ull*)(Ws + (tc + j * 16) * WS + 2 * kp);
        #pragma unroll
        for (int i = 0; i < 8; i++)
            #pragma unroll
            for (int j = 0; j < CPT; j++)
                acc[i][j] = fma2(a2[i], b2[j], acc[i][j]);
    }

    float bv[CPT];
    #pragma unroll
    for (int j = 0; j < CPT; j++) bv[j] = __ldg(bias + tc + j * 16);

    float csum[CPT], csq[CPT];
    #pragma unroll
    for (int j = 0; j < CPT; j++) { csum[j] = 0.f; csq[j] = 0.f; }

    #pragma unroll
    for (int i = 0; i < 8; i++) {
        int gr = row0 + r0 + i;
        if (gr >= NN) continue;
        #pragma unroll
        for (int j = 0; j < CPT; j++) {
            float lo, hi;
            unpack2(acc[i][j], lo, hi);
            float v = lo + hi + bv[j];
            if (RELU) v = fmaxf(v, 0.f);
            if (STATS) { csum[j] += v; csq[j] += v * v; }
            out[(size_t)gr * NOUT + tc + j * 16] = v;
        }
    }

    if (STATS) {
        #pragma unroll
        for (int j = 0; j < CPT; j++) {
            atomicAdd(&s_sum[tc + j * 16], csum[j]);
            atomicAdd(&s_sq [tc + j * 16], csq[j]);
        }
        __syncthreads();
        if (tid < NOUT) {
            atomicAdd(&g_bnstats[tid], s_sum[tid]);
            atomicAdd(&g_bnstats[NOUT + tid], s_sq[tid]);
        }
    }
}

// ---------------- BN finalize ----------------
__global__ void bn_finalize_kernel(const float* __restrict__ gamma,
                                   const float* __restrict__ beta, int nout)
{
    int c = threadIdx.x;
    if (c < nout) {
        const float invN = 1.0f / (float)NN;
        float mu  = g_bnstats[c] * invN;
        float var = g_bnstats[nout + c] * invN - mu * mu;
        float s   = gamma[c] * rsqrtf(var + BN_EPS);
        g_scale[c] = s;
        g_shift[c] = beta[c] - mu * s;
    }
}

// ---------------- pooling (BN+ReLU fused) ----------------
__global__ void pool_sum_kernel(const float* __restrict__ pre, const int* __restrict__ batch)
{
    int t = blockIdx.x * blockDim.x + threadIdx.x;
    if (t >= NN * 16) return;
    int n = t >> 4, q = t & 15;
    int c = q << 2;
    int b = __ldg(batch + n);
    float4 v  = *(const float4*)(pre + (size_t)n * DO_ + c);
    float4 sc = *(const float4*)(g_scale + c);
    float4 sh = *(const float4*)(g_shift + c);
    v.x = fmaxf(fmaf(v.x, sc.x, sh.x), 0.f);
    v.y = fmaxf(fmaf(v.y, sc.y, sh.y), 0.f);
    v.z = fmaxf(fmaf(v.z, sc.z, sh.z), 0.f);
    v.w = fmaxf(fmaf(v.w, sc.w, sh.w), 0.f);
    float* p = g_pool + b * DO_ + c;
    asm volatile("red.global.add.v4.f32 [%0], {%1, %2, %3, %4};"
                 :: "l"(p), "f"(v.x), "f"(v.y), "f"(v.z), "f"(v.w) : "memory");
}

__global__ void pool_cnt_kernel(const int* __restrict__ batch)
{
    __shared__ int sc[NGR];
    for (int i = threadIdx.x; i < NGR; i += blockDim.x) sc[i] = 0;
    __syncthreads();
    for (int i = blockIdx.x * blockDim.x + threadIdx.x; i < NN; i += gridDim.x * blockDim.x)
        atomicAdd(&sc[__ldg(batch + i)], 1);
    __syncthreads();
    for (int i = threadIdx.x; i < NGR; i += blockDim.x)
        if (sc[i]) atomicAdd(&g_cnt[i], sc[i]);
}

__global__ void pool_fin_kernel(float* __restrict__ out)
{
    int i = blockIdx.x * blockDim.x + threadIdx.x;
    if (i < NGR * DO_) {
        int g = i >> 6;
        float c = (float)(g_cnt[g] > 0 ? g_cnt[g] : 1);
        out[i] = g_pool[i] / c;
    }
}

// ---------------- launcher ----------------
extern "C" void kernel_launch(void* const* d_in, const int* in_sizes, int n_in,
                              void* d_out, int out_size)
{
    const float* x     = (const float*)d_in[0];
    const int*   ei    = (const int*)d_in[1];
    const int*   batch = (const int*)d_in[2];
    const float *wA[3], *bA[3], *wB[3], *bB[3], *gam[3], *bet[3];
    for (int l = 0; l < 3; l++) {
        wA[l]  = (const float*)d_in[3 + 6*l + 0];
        bA[l]  = (const float*)d_in[3 + 6*l + 1];
        wB[l]  = (const float*)d_in[3 + 6*l + 2];
        bB[l]  = (const float*)d_in[3 + 6*l + 3];
        gam[l] = (const float*)d_in[3 + 6*l + 4];
        bet[l] = (const float*)d_in[3 + 6*l + 5];
    }
    const int* src = ei;
    const int* dst = ei + NE;

    float *agg, *hid, *h1, *h2, *bnst, *pool;
    int *cnt, *deg;
    cudaGetSymbolAddress((void**)&agg,  g_agg);
    cudaGetSymbolAddress((void**)&hid,  g_hid);
    cudaGetSymbolAddress((void**)&h1,   g_h1);
    cudaGetSymbolAddress((void**)&h2,   g_h2);
    cudaGetSymbolAddress((void**)&bnst, g_bnstats);
    cudaGetSymbolAddress((void**)&pool, g_pool);
    cudaGetSymbolAddress((void**)&cnt,  g_cnt);
    cudaGetSymbolAddress((void**)&deg,  g_deg);

    constexpr int SM128 = (128*128 + 128*130 + 2*128) * 4;  // 133120 B
    constexpr int SM64  = (128*128 +  64*130 + 2*64 ) * 4;  //  99328 B
    cudaFuncSetAttribute(gemm_kernel<128, true,  false>, cudaFuncAttributeMaxDynamicSharedMemorySize, SM128);
    cudaFuncSetAttribute(gemm_kernel<128, false, true >, cudaFuncAttributeMaxDynamicSharedMemorySize, SM128);
    cudaFuncSetAttribute(gemm_kernel<64,  false, true >, cudaFuncAttributeMaxDynamicSharedMemorySize, SM64);

    const int GB  = (NN + 127) / 128;          // 782
    const int EG  = (NE + 255) / 256;          // edge-parallel grid
    const int GG  = (NN + 7) / 8;              // gather grid (8 warps/block)

    // ---- CSR build (deterministic, rebuilt every replay) ----
    zero_kernel<<<(NN/4 + 255)/256, 256>>>((float*)deg, NN/4);
    hist_kernel<<<EG, 256>>>(dst);
    scan_pass1<<<NBLK, 256>>>();
    scan_pass2<<<1, 64>>>();
    scan_pass3<<<NBLK, 256>>>();
    fill_kernel<<<EG, 256>>>(src, dst);

    // ---- zero pool accumulators ----
    zero_kernel<<<(NGR * DO_ / 4 + 255)/256, 256>>>(pool, NGR * DO_ / 4);
    zero_kernel<<<1, 32>>>((float*)cnt, NGR / 4);

    // ---- layer 0 ----
    gather_kernel<false><<<GG, 256>>>(x, agg);
    gemm_kernel<128, true,  false><<<GB, 256, SM128>>>(agg, wA[0], bA[0], hid);
    zero_kernel<<<1, 64>>>(bnst, 64);
    gemm_kernel<128, false, true ><<<GB, 256, SM128>>>(hid, wB[0], bB[0], h1);   // pre-BN
    bn_finalize_kernel<<<1, 128>>>(gam[0], bet[0], 128);

    // ---- layer 1 (gather applies layer-0 BN+ReLU on the fly) ----
    gather_kernel<true><<<GG, 256>>>(h1, agg);
    gemm_kernel<128, true,  false><<<GB, 256, SM128>>>(agg, wA[1], bA[1], hid);
    zero_kernel<<<1, 64>>>(bnst, 64);
    gemm_kernel<128, false, true ><<<GB, 256, SM128>>>(hid, wB[1], bB[1], h2);   // pre-BN
    bn_finalize_kernel<<<1, 128>>>(gam[1], bet[1], 128);

    // ---- layer 2 ----
    gather_kernel<true><<<GG, 256>>>(h2, agg);
    gemm_kernel<128, true,  false><<<GB, 256, SM128>>>(agg, wA[2], bA[2], hid);
    zero_kernel<<<1, 64>>>(bnst, 64);
    gemm_kernel<64,  false, true ><<<GB, 256, SM64 >>>(hid, wB[2], bB[2], h1);   // pre-BN (64)
    bn_finalize_kernel<<<1, 64>>>(gam[2], bet[2], 64);

    // ---- global mean pool (BN+ReLU fused into the sum) ----
    pool_sum_kernel<<<(NN * 16 + 255)/256, 256>>>(h1, batch);
    pool_cnt_kernel<<<296, 256>>>(batch);
    pool_fin_kernel<<<(NGR * DO_ + 255)/256, 256>>>((float*)d_out);
}

// round 4
// speedup vs baseline: 1.9691x; 1.6456x over previous
#include <cuda_runtime.h>
#include <cuda_bf16.h>
#include <cstdint>

#define NN   100000
#define NE   1600000
#define NGR  128
#define D_   128
#define DO_  64
#define BN_EPS 1e-5f
#define SCAN_ELEMS 2048
#define NBLK ((NN + SCAN_ELEMS - 1) / SCAN_ELEMS)   // 49

typedef unsigned long long ull;

// ---------------- scratch ----------------
__device__ __align__(16) float g_agg[(size_t)NN * D_];
__device__ __align__(16) float g_hid[(size_t)NN * D_];
__device__ __align__(16) float g_h1 [(size_t)NN * D_];
__device__ __align__(16) float g_h2 [(size_t)NN * D_];
__device__ __align__(16) float g_bnstats[2 * D_];
__device__ __align__(16) float g_scale[D_];
__device__ __align__(16) float g_shift[D_];
__device__ __align__(16) float g_pool[NGR * DO_];
__device__ __align__(16) int   g_cnt[NGR];
// CSR scratch
__device__ __align__(16) int g_deg[NN];
__device__ __align__(16) int g_off[NN + 1];
__device__ __align__(16) int g_cur[NN];
__device__ __align__(16) int g_csr[NE];
__device__ int g_bsum[64];
__device__ int g_bscan[64];
// pre-split, pre-swizzled W images: [k][n] row-major bf16, 16B-chunk XOR swizzle
__device__ __align__(16) unsigned char g_whi[6 * 32768];
__device__ __align__(16) unsigned char g_wlo[6 * 32768];

// ---------------- asm helpers ----------------
__device__ __forceinline__ uint32_t smem_u32(const void* p) {
    uint32_t a;
    asm("{ .reg .u64 t; cvta.to.shared.u64 t, %1; cvt.u32.u64 %0, t; }" : "=r"(a) : "l"(p));
    return a;
}
__device__ __forceinline__ void ldsm_x4(uint32_t& r0, uint32_t& r1, uint32_t& r2, uint32_t& r3,
                                        uint32_t addr) {
    asm volatile("ldmatrix.sync.aligned.m8n8.x4.shared.b16 {%0,%1,%2,%3}, [%4];"
                 : "=r"(r0), "=r"(r1), "=r"(r2), "=r"(r3) : "r"(addr));
}
__device__ __forceinline__ void ldsm_x4t(uint32_t& r0, uint32_t& r1, uint32_t& r2, uint32_t& r3,
                                         uint32_t addr) {
    asm volatile("ldmatrix.sync.aligned.m8n8.x4.trans.shared.b16 {%0,%1,%2,%3}, [%4];"
                 : "=r"(r0), "=r"(r1), "=r"(r2), "=r"(r3) : "r"(addr));
}
__device__ __forceinline__ void mma16816(float* c, uint32_t a0, uint32_t a1, uint32_t a2,
                                         uint32_t a3, uint32_t b0, uint32_t b1) {
    asm volatile("mma.sync.aligned.m16n8k16.row.col.f32.bf16.bf16.f32 "
                 "{%0,%1,%2,%3}, {%4,%5,%6,%7}, {%8,%9}, {%0,%1,%2,%3};"
                 : "+f"(c[0]), "+f"(c[1]), "+f"(c[2]), "+f"(c[3])
                 : "r"(a0), "r"(a1), "r"(a2), "r"(a3), "r"(b0), "r"(b1));
}

// ---------------- utility ----------------
__global__ void zero_kernel(float* __restrict__ p, int n4) {
    int i = blockIdx.x * blockDim.x + threadIdx.x;
    if (i < n4) ((float4*)p)[i] = make_float4(0.f, 0.f, 0.f, 0.f);
}

// ---------------- CSR build ----------------
__global__ void hist_kernel(const int* __restrict__ dst) {
    int i = blockIdx.x * blockDim.x + threadIdx.x;
    if (i < NE) atomicAdd(&g_deg[__ldg(dst + i)], 1);
}
__global__ void scan_pass1() {
    __shared__ int ssum[8];
    int b = blockIdx.x, tid = threadIdx.x;
    int base = b * SCAN_ELEMS + tid * 8;
    int s = 0;
    #pragma unroll
    for (int j = 0; j < 8; j++) { int idx = base + j; s += (idx < NN) ? g_deg[idx] : 0; }
    #pragma unroll
    for (int o = 16; o; o >>= 1) s += __shfl_down_sync(0xffffffffu, s, o);
    if ((tid & 31) == 0) ssum[tid >> 5] = s;
    __syncthreads();
    if (tid == 0) {
        int t = 0;
        #pragma unroll
        for (int i = 0; i < 8; i++) t += ssum[i];
        g_bsum[b] = t;
    }
}
__global__ void scan_pass2() {
    int tid = threadIdx.x;
    int v = (tid < NBLK) ? g_bsum[tid] : 0;
    int incl = v, lane = tid & 31;
    #pragma unroll
    for (int o = 1; o < 32; o <<= 1) {
        int y = __shfl_up_sync(0xffffffffu, incl, o);
        if (lane >= o) incl += y;
    }
    __shared__ int w0;
    if (tid == 31) w0 = incl;
    __syncthreads();
    if (tid >= 32) incl += w0;
    if (tid < 64) g_bscan[tid] = incl - v;
    if (tid == 0) g_off[NN] = NE;
}
__global__ void scan_pass3() {
    int b = blockIdx.x, tid = threadIdx.x;
    int base = b * SCAN_ELEMS + tid * 8;
    int vals[8], t = 0;
    #pragma unroll
    for (int j = 0; j < 8; j++) { vals[j] = (base + j < NN) ? g_deg[base + j] : 0; t += vals[j]; }
    int lane = tid & 31, wid = tid >> 5, incl = t;
    #pragma unroll
    for (int o = 1; o < 32; o <<= 1) {
        int y = __shfl_up_sync(0xffffffffu, incl, o);
        if (lane >= o) incl += y;
    }
    __shared__ int wsum[8], woff[8];
    if (lane == 31) wsum[wid] = incl;
    __syncthreads();
    if (tid == 0) { int a = 0; for (int i = 0; i < 8; i++) { woff[i] = a; a += wsum[i]; } }
    __syncthreads();
    int run = g_bscan[b] + woff[wid] + (incl - t);
    #pragma unroll
    for (int j = 0; j < 8; j++) {
        int idx = base + j;
        if (idx < NN) { g_off[idx] = run; g_cur[idx] = run; run += vals[j]; }
    }
}
__global__ void fill_kernel(const int* __restrict__ src, const int* __restrict__ dst) {
    int i = blockIdx.x * blockDim.x + threadIdx.x;
    if (i < NE) {
        int d = __ldg(dst + i);
        int p = atomicAdd(&g_cur[d], 1);
        g_csr[p] = __ldg(src + i);
    }
}

// ---------------- W split + swizzle preconvert ----------------
// layout: [k][n] row-major bf16, within-row 16B chunk c=n>>3 stored at c ^ (k & 7)
__global__ void wconv_kernel(const float* w0, const float* w1, const float* w2,
                             const float* w3, const float* w4, const float* w5)
{
    int i = blockIdx.x * blockDim.x + threadIdx.x;
    if (i >= 5 * 16384 + 8192) return;
    int seg = i >> 14;
    int t = i & 16383;
    int nout = (seg == 5) ? 64 : 128;
    const float* W = (seg == 0) ? w0 : (seg == 1) ? w1 : (seg == 2) ? w2
                   : (seg == 3) ? w3 : (seg == 4) ? w4 : w5;
    int k = t / nout, n = t % nout;
    float w = __ldg(W + k * nout + n);
    __nv_bfloat16 hi = __float2bfloat16(w);
    __nv_bfloat16 lo = __float2bfloat16(w - __bfloat162float(hi));
    int pos = k * nout + ((((n >> 3) ^ (k & 7)) << 3) | (n & 7));
    ((__nv_bfloat16*)(g_whi + seg * 32768))[pos] = hi;
    ((__nv_bfloat16*)(g_wlo + seg * 32768))[pos] = lo;
}

// ---------------- gather ----------------
__device__ __forceinline__ float4 bn_ap(float4 v, float4 sc, float4 sh, bool bn) {
    if (bn) {
        v.x = fmaxf(fmaf(v.x, sc.x, sh.x), 0.f);
        v.y = fmaxf(fmaf(v.y, sc.y, sh.y), 0.f);
        v.z = fmaxf(fmaf(v.z, sc.z, sh.z), 0.f);
        v.w = fmaxf(fmaf(v.w, sc.w, sh.w), 0.f);
    }
    return v;
}
__device__ __forceinline__ void f4acc(float4& a, float4 b) {
    a.x += b.x; a.y += b.y; a.z += b.z; a.w += b.w;
}

template<bool BN>
__global__ void gather_kernel(const float* __restrict__ h, float* __restrict__ out)
{
    int n = blockIdx.x * 8 + (threadIdx.x >> 5);
    if (n >= NN) return;
    int lane = threadIdx.x & 31;
    const float4* __restrict__ h4 = (const float4*)h;

    float4 sc = make_float4(0,0,0,0), sh = make_float4(0,0,0,0);
    if (BN) {
        sc = *(const float4*)(g_scale + lane * 4);
        sh = *(const float4*)(g_shift + lane * 4);
    }
    float4 a0 = bn_ap(__ldg(&h4[(size_t)n * 32 + lane]), sc, sh, BN);
    float4 a1 = make_float4(0,0,0,0), a2 = make_float4(0,0,0,0), a3 = make_float4(0,0,0,0);

    int j = g_off[n], e1 = g_off[n + 1];
    for (; j + 4 <= e1; j += 4) {
        int i0 = __ldg(&g_csr[j]);
        int i1 = __ldg(&g_csr[j + 1]);
        int i2 = __ldg(&g_csr[j + 2]);
        int i3 = __ldg(&g_csr[j + 3]);
        float4 w0 = __ldg(&h4[(size_t)i0 * 32 + lane]);
        float4 w1 = __ldg(&h4[(size_t)i1 * 32 + lane]);
        float4 w2 = __ldg(&h4[(size_t)i2 * 32 + lane]);
        float4 w3 = __ldg(&h4[(size_t)i3 * 32 + lane]);
        f4acc(a0, bn_ap(w0, sc, sh, BN));
        f4acc(a1, bn_ap(w1, sc, sh, BN));
        f4acc(a2, bn_ap(w2, sc, sh, BN));
        f4acc(a3, bn_ap(w3, sc, sh, BN));
    }
    for (; j < e1; j++) {
        int s = __ldg(&g_csr[j]);
        f4acc(a0, bn_ap(__ldg(&h4[(size_t)s * 32 + lane]), sc, sh, BN));
    }
    f4acc(a0, a1); f4acc(a2, a3); f4acc(a0, a2);
    ((float4*)out)[(size_t)n * 32 + lane] = a0;
}

// ---------------- tensor-core GEMM (mma.sync, split-bf16 3-term) ----------------
// out[N,NOUT] = A[N,128] @ W[128,NOUT] + bias ; 256 thr, 128-row tile,
// warp w handles rows [16w, 16w+16), all NOUT cols. Full K in smem.
template<int NOUT, bool RELU>
__global__ __launch_bounds__(256, 1)
void gemm_mma(const float* __restrict__ A,
              const unsigned char* __restrict__ wh, const unsigned char* __restrict__ wl,
              const float* __restrict__ bias, float* __restrict__ out)
{
    constexpr int NT  = NOUT / 8;       // n8 tiles: 16 or 8
    constexpr int BR  = NOUT * 2;       // B row bytes
    constexpr int AHI = 0;
    constexpr int ALO = 32768;
    constexpr int BHI = 65536;
    constexpr int BLO = 65536 + 128 * BR;

    extern __shared__ __align__(16) char smem[];
    const uint32_t sb = smem_u32(smem);
    const int tid  = threadIdx.x;
    const int wid  = tid >> 5;
    const int lane = tid & 31;
    const int row0 = blockIdx.x * 128;

    // B tiles: straight copy of pre-swizzled images
    {
        const float4* s1 = (const float4*)wh;
        const float4* s2 = (const float4*)wl;
        float4* d1 = (float4*)(smem + BHI);
        float4* d2 = (float4*)(smem + BLO);
        #pragma unroll
        for (int i = tid; i < NOUT * 16; i += 256) { d1[i] = s1[i]; d2[i] = s2[i]; }
    }
    // A tile: fp32 -> bf16 hi/lo, swizzled 16B chunks (chunk c at c ^ (r&7))
    for (int i = tid; i < 2048; i += 256) {
        int r = i >> 4, c = i & 15;
        int gr = row0 + r;
        float4 v0 = make_float4(0,0,0,0), v1 = make_float4(0,0,0,0);
        if (gr < NN) {
            const float4* ap = (const float4*)(A + (size_t)gr * 128 + c * 8);
            v0 = __ldg(ap); v1 = __ldg(ap + 1);
        }
        float vv[8] = {v0.x, v0.y, v0.z, v0.w, v1.x, v1.y, v1.z, v1.w};
        uint4 hq, lq;
        uint32_t* hp = (uint32_t*)&hq;
        uint32_t* lp = (uint32_t*)&lq;
        #pragma unroll
        for (int p = 0; p < 4; p++) {
            __nv_bfloat162 h2, l2;
            h2.x = __float2bfloat16(vv[2*p]);
            h2.y = __float2bfloat16(vv[2*p+1]);
            l2.x = __float2bfloat16(vv[2*p]   - __bfloat162float(h2.x));
            l2.y = __float2bfloat16(vv[2*p+1] - __bfloat162float(h2.y));
            hp[p] = *(uint32_t*)&h2;
            lp[p] = *(uint32_t*)&l2;
        }
        uint32_t off = (uint32_t)(r * 256 + ((c ^ (r & 7)) << 4));
        *(uint4*)(smem + AHI + off) = hq;
        *(uint4*)(smem + ALO + off) = lq;
    }
    __syncthreads();

    // mainloop
    const int la = lane & 15;          // row-within / k-row select
    const int lb = lane >> 4;          // 0/1: second chunk
    const int l7 = lane & 7;
    const uint32_t aRow = (uint32_t)((wid * 16 + la) * 256);
    const uint32_t bRow = (uint32_t)(la * BR);

    float acc[NT][4];
    #pragma unroll
    for (int t = 0; t < NT; t++)
        #pragma unroll
        for (int e = 0; e < 4; e++) acc[t][e] = 0.f;

    #pragma unroll 2
    for (int k0 = 0; k0 < 128; k0 += 16) {
        uint32_t kc = (uint32_t)((k0 >> 3) + lb);
        uint32_t aoff = aRow + (((kc ^ (uint32_t)l7)) << 4);
        uint32_t ah0, ah1, ah2, ah3, al0, al1, al2, al3;
        ldsm_x4(ah0, ah1, ah2, ah3, sb + AHI + aoff);
        ldsm_x4(al0, al1, al2, al3, sb + ALO + aoff);
        uint32_t bbase = (uint32_t)(k0 * BR) + bRow;
        #pragma unroll
        for (int nt = 0; nt < NT; nt += 2) {
            uint32_t boff = bbase + ((((uint32_t)(nt + lb)) ^ (uint32_t)l7) << 4);
            uint32_t bh0, bh1, bh2, bh3, bl0, bl1, bl2, bl3;
            ldsm_x4t(bh0, bh1, bh2, bh3, sb + BHI + boff);
            ldsm_x4t(bl0, bl1, bl2, bl3, sb + BLO + boff);
            mma16816(acc[nt],     ah0, ah1, ah2, ah3, bh0, bh1);
            mma16816(acc[nt + 1], ah0, ah1, ah2, ah3, bh2, bh3);
            mma16816(acc[nt],     ah0, ah1, ah2, ah3, bl0, bl1);
            mma16816(acc[nt + 1], ah0, ah1, ah2, ah3, bl2, bl3);
            mma16816(acc[nt],     al0, al1, al2, al3, bh0, bh1);
            mma16816(acc[nt + 1], al0, al1, al2, al3, bh2, bh3);
        }
    }

    // epilogue: lane l -> rows (l/4, l/4+8), cols 2*(l%4)+... per n8 tile
    int r1 = row0 + wid * 16 + (lane >> 2);
    int r2 = r1 + 8;
    #pragma unroll
    for (int nt = 0; nt < NT; nt++) {
        int col = nt * 8 + (lane & 3) * 2;
        float2 bb = __ldg((const float2*)(bias + col));
        float v0 = acc[nt][0] + bb.x;
        float v1 = acc[nt][1] + bb.y;
        float v2 = acc[nt][2] + bb.x;
        float v3 = acc[nt][3] + bb.y;
        if (RELU) {
            v0 = fmaxf(v0, 0.f); v1 = fmaxf(v1, 0.f);
            v2 = fmaxf(v2, 0.f); v3 = fmaxf(v3, 0.f);
        }
        if (r1 < NN) *(float2*)(out + (size_t)r1 * NOUT + col) = make_float2(v0, v1);
        if (r2 < NN) *(float2*)(out + (size_t)r2 * NOUT + col) = make_float2(v2, v3);
    }
}

// ---------------- BN column stats ----------------
template<int NOUT>
__global__ void stats_kernel(const float* __restrict__ h)
{
    constexpr int QC = NOUT / 4;
    constexpr int STEP = 256 / QC;
    __shared__ float ss[NOUT], sq[NOUT];
    int tid = threadIdx.x;
    if (tid < NOUT) { ss[tid] = 0.f; sq[tid] = 0.f; }
    __syncthreads();
    int qc = tid % QC, rg = tid / QC;
    int rend = min(blockIdx.x * 512 + 512, NN);
    float4 s4 = make_float4(0,0,0,0), q4 = make_float4(0,0,0,0);
    for (int r = blockIdx.x * 512 + rg; r < rend; r += STEP) {
        float4 v = __ldg((const float4*)(h + (size_t)r * NOUT) + qc);
        s4.x += v.x; s4.y += v.y; s4.z += v.z; s4.w += v.w;
        q4.x += v.x*v.x; q4.y += v.y*v.y; q4.z += v.z*v.z; q4.w += v.w*v.w;
    }
    int c = qc * 4;
    atomicAdd(&ss[c+0], s4.x); atomicAdd(&ss[c+1], s4.y);
    atomicAdd(&ss[c+2], s4.z); atomicAdd(&ss[c+3], s4.w);
    atomicAdd(&sq[c+0], q4.x); atomicAdd(&sq[c+1], q4.y);
    atomicAdd(&sq[c+2], q4.z); atomicAdd(&sq[c+3], q4.w);
    __syncthreads();
    if (tid < NOUT) {
        atomicAdd(&g_bnstats[tid], ss[tid]);
        atomicAdd(&g_bnstats[NOUT + tid], sq[tid]);
    }
}

__global__ void bn_finalize_kernel(const float* __restrict__ gamma,
                                   const float* __restrict__ beta, int nout)
{
    int c = threadIdx.x;
    if (c < nout) {
        const float invN = 1.0f / (float)NN;
        float mu  = g_bnstats[c] * invN;
        float var = g_bnstats[nout + c] * invN - mu * mu;
        float s   = gamma[c] * rsqrtf(var + BN_EPS);
        g_scale[c] = s;
        g_shift[c] = beta[c] - mu * s;
    }
}

// ---------------- pooling (BN+ReLU fused) ----------------
__global__ void pool_sum_kernel(const float* __restrict__ pre, const int* __restrict__ batch)
{
    int t = blockIdx.x * blockDim.x + threadIdx.x;
    if (t >= NN * 16) return;
    int n = t >> 4, q = t & 15;
    int c = q << 2;
    int b = __ldg(batch + n);
    float4 v  = *(const float4*)(pre + (size_t)n * DO_ + c);
    float4 sc = *(const float4*)(g_scale + c);
    float4 sh = *(const float4*)(g_shift + c);
    v.x = fmaxf(fmaf(v.x, sc.x, sh.x), 0.f);
    v.y = fmaxf(fmaf(v.y, sc.y, sh.y), 0.f);
    v.z = fmaxf(fmaf(v.z, sc.z, sh.z), 0.f);
    v.w = fmaxf(fmaf(v.w, sc.w, sh.w), 0.f);
    float* p = g_pool + b * DO_ + c;
    asm volatile("red.global.add.v4.f32 [%0], {%1, %2, %3, %4};"
                 :: "l"(p), "f"(v.x), "f"(v.y), "f"(v.z), "f"(v.w) : "memory");
}

__global__ void pool_cnt_kernel(const int* __restrict__ batch)
{
    __shared__ int sc[NGR];
    for (int i = threadIdx.x; i < NGR; i += blockDim.x) sc[i] = 0;
    __syncthreads();
    for (int i = blockIdx.x * blockDim.x + threadIdx.x; i < NN; i += gridDim.x * blockDim.x)
        atomicAdd(&sc[__ldg(batch + i)], 1);
    __syncthreads();
    for (int i = threadIdx.x; i < NGR; i += blockDim.x)
        if (sc[i]) atomicAdd(&g_cnt[i], sc[i]);
}

__global__ void pool_fin_kernel(float* __restrict__ out)
{
    int i = blockIdx.x * blockDim.x + threadIdx.x;
    if (i < NGR * DO_) {
        int g = i >> 6;
        float c = (float)(g_cnt[g] > 0 ? g_cnt[g] : 1);
        out[i] = g_pool[i] / c;
    }
}

// ---------------- launcher ----------------
extern "C" void kernel_launch(void* const* d_in, const int* in_sizes, int n_in,
                              void* d_out, int out_size)
{
    const float* x     = (const float*)d_in[0];
    const int*   ei    = (const int*)d_in[1];
    const int*   batch = (const int*)d_in[2];
    const float *wA[3], *bA[3], *wB[3], *bB[3], *gam[3], *bet[3];
    for (int l = 0; l < 3; l++) {
        wA[l]  = (const float*)d_in[3 + 6*l + 0];
        bA[l]  = (const float*)d_in[3 + 6*l + 1];
        wB[l]  = (const float*)d_in[3 + 6*l + 2];
        bB[l]  = (const float*)d_in[3 + 6*l + 3];
        gam[l] = (const float*)d_in[3 + 6*l + 4];
        bet[l] = (const float*)d_in[3 + 6*l + 5];
    }
    const int* src = ei;
    const int* dst = ei + NE;

    float *agg, *hid, *h1, *h2, *bnst, *pool;
    int *cnt, *deg;
    unsigned char *whi, *wlo;
    cudaGetSymbolAddress((void**)&agg,  g_agg);
    cudaGetSymbolAddress((void**)&hid,  g_hid);
    cudaGetSymbolAddress((void**)&h1,   g_h1);
    cudaGetSymbolAddress((void**)&h2,   g_h2);
    cudaGetSymbolAddress((void**)&bnst, g_bnstats);
    cudaGetSymbolAddress((void**)&pool, g_pool);
    cudaGetSymbolAddress((void**)&cnt,  g_cnt);
    cudaGetSymbolAddress((void**)&deg,  g_deg);
    cudaGetSymbolAddress((void**)&whi,  g_whi);
    cudaGetSymbolAddress((void**)&wlo,  g_wlo);

    constexpr int SM128 = 65536 + 2 * 128 * 256;  // 131072
    constexpr int SM64  = 65536 + 2 * 64  * 256;  //  98304
    cudaFuncSetAttribute(gemm_mma<128, true >, cudaFuncAttributeMaxDynamicSharedMemorySize, SM128);
    cudaFuncSetAttribute(gemm_mma<128, false>, cudaFuncAttributeMaxDynamicSharedMemorySize, SM128);
    cudaFuncSetAttribute(gemm_mma<64,  false>, cudaFuncAttributeMaxDynamicSharedMemorySize, SM64);

    const int GB = (NN + 127) / 128;   // 782
    const int EG = (NE + 255) / 256;
    const int GG = (NN + 7) / 8;
    const int SG = (NN + 511) / 512;

    // ---- CSR build ----
    zero_kernel<<<(NN/4 + 255)/256, 256>>>((float*)deg, NN/4);
    hist_kernel<<<EG, 256>>>(dst);
    scan_pass1<<<NBLK, 256>>>();
    scan_pass2<<<1, 64>>>();
    scan_pass3<<<NBLK, 256>>>();
    fill_kernel<<<EG, 256>>>(src, dst);

    // ---- W preconvert + zero accumulators ----
    wconv_kernel<<<(5*16384 + 8192 + 255)/256, 256>>>(wA[0], wB[0], wA[1], wB[1], wA[2], wB[2]);
    zero_kernel<<<(NGR * DO_ / 4 + 255)/256, 256>>>(pool, NGR * DO_ / 4);
    zero_kernel<<<1, 32>>>((float*)cnt, NGR / 4);

    // ---- layer 0 ----
    gather_kernel<false><<<GG, 256>>>(x, agg);
    gemm_mma<128, true ><<<GB, 256, SM128>>>(agg, whi + 0*32768, wlo + 0*32768, bA[0], hid);
    gemm_mma<128, false><<<GB, 256, SM128>>>(hid, whi + 1*32768, wlo + 1*32768, bB[0], h1);
    zero_kernel<<<1, 64>>>(bnst, 64);
    stats_kernel<128><<<SG, 256>>>(h1);
    bn_finalize_kernel<<<1, 128>>>(gam[0], bet[0], 128);

    // ---- layer 1 ----
    gather_kernel<true><<<GG, 256>>>(h1, agg);
    gemm_mma<128, true ><<<GB, 256, SM128>>>(agg, whi + 2*32768, wlo + 2*32768, bA[1], hid);
    gemm_mma<128, false><<<GB, 256, SM128>>>(hid, whi + 3*32768, wlo + 3*32768, bB[1], h2);
    zero_kernel<<<1, 64>>>(bnst, 64);
    stats_kernel<128><<<SG, 256>>>(h2);
    bn_finalize_kernel<<<1, 128>>>(gam[1], bet[1], 128);

    // ---- layer 2 ----
    gather_kernel<true><<<GG, 256>>>(h2, agg);
    gemm_mma<128, true ><<<GB, 256, SM128>>>(agg, whi + 4*32768, wlo + 4*32768, bA[2], hid);
    gemm_mma<64,  false><<<GB, 256, SM64 >>>(hid, whi + 5*32768, wlo + 5*32768, bB[2], h1);
    zero_kernel<<<1, 64>>>(bnst, 64);
    stats_kernel<64><<<SG, 256>>>(h1);
    bn_finalize_kernel<<<1, 64>>>(gam[2], bet[2], 64);

    // ---- global mean pool (BN+ReLU fused) ----
    pool_sum_kernel<<<(NN * 16 + 255)/256, 256>>>(h1, batch);
    pool_cnt_kernel<<<296, 256>>>(batch);
    pool_fin_kernel<<<(NGR * DO_ + 255)/256, 256>>>((float*)d_out);
}